// round 10
// baseline (speedup 1.0000x reference)
#include <cuda_runtime.h>
#include <math.h>

#define GRID 128
#define NT 512

// ---------------- scratch ----------------
__device__ __align__(16) float g_Ppart[16 * 32 * 1024]; // [chunk][o][d]
__device__ __align__(16) float g_MTp[4 * 16 * 1024];    // [quarter][n][d]
__device__ __align__(16) float g_PpD[1024 * 64];        // [k][{o,o} duplicated]
__device__ __align__(16) float g_MT[16 * 1024];         // [n][d]
__device__ float g_c[32];
__device__ float g_k1[32];
__device__ float g_k2[32];
__device__ __align__(16) float g_au[2 * 32 * 4096];     // [b][o][s]
__device__ __align__(16) float g_states[2 * 16 * 4096]; // [b*16+n][s]
__device__ int g_cnt;                                   // barrier (monotonic)

typedef unsigned long long ull;
__device__ __forceinline__ ull dup_f(float v) {
    ull r; asm("mov.b64 %0, {%1, %1};" : "=l"(r) : "f"(v)); return r;
}
#define FFMA2(acc, a, b) asm("fma.rn.f32x2 %0, %1, %2, %0;" : "+l"(acc) : "l"(a), "l"(b))
#define ADD2(acc, a)     asm("add.rn.f32x2 %0, %0, %1;" : "+l"(acc) : "l"(a))
__device__ __forceinline__ void unpk(float& lo, float& hi, ull v) {
    asm("mov.b64 {%0, %1}, %2;" : "=f"(lo), "=f"(hi) : "l"(v));
}
__device__ __forceinline__ void cp16(unsigned int dst, const void* src) {
    asm volatile("cp.async.ca.shared.global [%0], [%1], 16;" :: "r"(dst), "l"(src));
}

// grid-wide barrier: monotonic counter, replay-safe
__device__ __forceinline__ void gsync() {
    __syncthreads();
    if (threadIdx.x == 0) {
        __threadfence();
        int arrival = atomicAdd(&g_cnt, 1);
        int target = (arrival / GRID + 1) * GRID;
        while (*((volatile int*)&g_cnt) < target) { }
        __threadfence();
    }
    __syncthreads();
}

// ---------------- single fused kernel ----------------
__global__ void __launch_bounds__(NT) k_main(const float* __restrict__ x,
                                             const float* __restrict__ nw,
                                             const float* __restrict__ nb,
                                             const float* __restrict__ Win,
                                             const float* __restrict__ b_in,
                                             const float* __restrict__ A,
                                             const float* __restrict__ Bs,
                                             const float* __restrict__ C,
                                             const float* __restrict__ Wout,
                                             const float* __restrict__ bo,
                                             float* __restrict__ out) {
    extern __shared__ float dsm[];   // 16896 floats = 67584 B
    int tid = threadIdx.x;
    int blk = blockIdx.x;
    int lane = tid & 31, wid = tid >> 5;

    // ================= P-1: prologue (split-K partials for P and MT, bias c) =================
    if (blk < 32) {
        // --- P partials: 2 units of 256 threads; unit = blk*2 + (tid>>8) ---
        ull* sAB2 = (ull*)dsm + (tid >> 8) * 4096;  // 32KB per unit
        int t2 = tid & 255;
        int unit = blk * 2 + (tid >> 8);
        int dt = unit >> 4;
        int chunk = unit & 15;
        int e0 = chunk * 128;
        for (int i = t2; i < 128 * 16; i += 256) {
            int el = i >> 4, n = i & 15;
            sAB2[el * 32 + n]      = dup_f(A [(e0 + el) * 16 + n]);
            sAB2[el * 32 + 16 + n] = dup_f(Bs[(e0 + el) * 16 + n]);
        }
        __syncthreads();
        int dp = t2 >> 1, oh = t2 & 1;
        int d = dt * 256 + dp * 2;
        ull acc[16];
#pragma unroll
        for (int o = 0; o < 16; o++) acc[o] = 0ull;
#pragma unroll 4
        for (int el = 0; el < 128; el++) {
            ull w01 = *(const ull*)(Win + (e0 + el) * 1024 + d);
            const ull* base = sAB2 + el * 32 + oh * 16;
#pragma unroll
            for (int o = 0; o < 16; o++) FFMA2(acc[o], w01, base[o]);
        }
#pragma unroll
        for (int o = 0; o < 16; o++) {
            int oi = oh * 16 + o;
            *(ull*)(g_Ppart + (chunk * 32 + oi) * 1024 + d) = acc[o];
        }
    } else if (blk < 64) {
        // --- MT partials: 2 units of 256 threads ---
        float* sC = dsm + (tid >> 8) * 2048;   // 8KB per unit
        int t2 = tid & 255;
        int unit = (blk - 32) * 2 + (tid >> 8);
        int tile = unit >> 2;
        int q = unit & 3;
        int row = tile * 64 + (t2 >> 2);
        int nq = t2 & 3;
        ull acc0 = 0ull, acc1 = 0ull;
        for (int c = 0; c < 4; c++) {
            int e0 = q * 512 + c * 128;
            __syncthreads();
            for (int i = t2; i < 512; i += 256)
                ((float4*)sC)[i] = ((const float4*)(C + e0 * 16))[i];
            __syncthreads();
            const float* wrow = Wout + row * 2048 + e0;
#pragma unroll 8
            for (int g = 0; g < 32; g++) {
                float4 w4 = *(const float4*)(wrow + g * 4);
#pragma unroll
                for (int j = 0; j < 4; j++) {
                    float wv = (j == 0) ? w4.x : (j == 1) ? w4.y : (j == 2) ? w4.z : w4.w;
                    ull wd = dup_f(wv);
                    ulonglong2 cp = *(const ulonglong2*)(sC + (g * 4 + j) * 16 + nq * 4);
                    FFMA2(acc0, wd, cp.x);
                    FFMA2(acc1, wd, cp.y);
                }
            }
        }
        float a[4];
        unpk(a[0], a[1], acc0);
        unpk(a[2], a[3], acc1);
#pragma unroll
        for (int i = 0; i < 4; i++) {
            int n = nq * 4 + i;
            g_MTp[(q * 16 + n) * 1024 + row] = a[i];
        }
    } else if (blk == 64) {
        // --- bias c = b_in @ {A|B}: 2 units of 256 threads ---
        float* red = dsm + (tid >> 8) * 128;
        int t2 = tid & 255;
        int half = tid >> 8;
        int l2 = t2 & 31, w2 = t2 >> 5;
        const float* G = half ? Bs : A;
        float acc[16];
#pragma unroll
        for (int n = 0; n < 16; n++) acc[n] = 0.f;
        for (int e = t2; e < 2048; e += 256) {
            float bv = b_in[e];
            const float4* g4 = (const float4*)(G + e * 16);
            float4 c0 = g4[0], c1 = g4[1], c2 = g4[2], c3 = g4[3];
            acc[0] += bv * c0.x; acc[1] += bv * c0.y; acc[2] += bv * c0.z; acc[3] += bv * c0.w;
            acc[4] += bv * c1.x; acc[5] += bv * c1.y; acc[6] += bv * c1.z; acc[7] += bv * c1.w;
            acc[8] += bv * c2.x; acc[9] += bv * c2.y; acc[10]+= bv * c2.z; acc[11]+= bv * c2.w;
            acc[12]+= bv * c3.x; acc[13]+= bv * c3.y; acc[14]+= bv * c3.z; acc[15]+= bv * c3.w;
        }
#pragma unroll
        for (int off = 16; off; off >>= 1)
#pragma unroll
            for (int n = 0; n < 16; n++) acc[n] += __shfl_down_sync(0xffffffffu, acc[n], off);
        if (l2 == 0) {
#pragma unroll
            for (int n = 0; n < 16; n++) red[w2 * 16 + n] = acc[n];
        }
        __syncthreads();
        if (t2 < 16) {
            float s = 0.f;
#pragma unroll
            for (int j = 0; j < 8; j++) s += red[j * 16 + t2];
            g_c[half * 16 + t2] = s;
        }
    }
    gsync();

    // ================= P0: fold =================
    if (blk < 32) {
        __shared__ float sred[32];
        int o = blk;
        float s1 = 0.f, s2 = 0.f;
#pragma unroll
        for (int h = 0; h < 2; h++) {
            int d = tid + h * 512;
            float p = 0.f;
#pragma unroll
            for (int c = 0; c < 16; c++) p += g_Ppart[(c * 32 + o) * 1024 + d];
            float pp = nw[d] * p;
            s1 += pp;
            s2 += nb[d] * p;
            *(float2*)&g_PpD[d * 64 + o * 2] = make_float2(pp, pp);
        }
#pragma unroll
        for (int off = 16; off; off >>= 1) {
            s1 += __shfl_down_sync(0xffffffffu, s1, off);
            s2 += __shfl_down_sync(0xffffffffu, s2, off);
        }
        if (lane == 0) { sred[wid] = s1; sred[16 + wid] = s2; }
        __syncthreads();
        if (tid == 0) {
            float S1 = 0.f, S2 = 0.f;
#pragma unroll
            for (int j = 0; j < 16; j++) { S1 += sred[j]; S2 += sred[16 + j]; }
            g_k1[o] = S1;
            g_k2[o] = S2 + g_c[o];
        }
    } else if (blk < 64) {
        int base = (blk - 32) * 512 + tid;
        int d = base & 1023, n = base >> 10;
        float s = 0.f;
#pragma unroll
        for (int q = 0; q < 4; q++) s += g_MTp[(q * 16 + n) * 1024 + d];
        g_MT[n * 1024 + d] = s;
    }
    gsync();

    // ================= P1: LN + projection =================
    {
        float* sXT = dsm;          // 2 x (64 k x 68) = 8704 floats
        float* sPD = dsm + 8704;   // 2 x (64 k x 64) = 8192 floats
        int tg = tid & 15;         // token quad
        int ks = (tid >> 4) & 3;   // k-split
        int og = tid >> 6;         // output quad (warp-uniform)
        int T0 = blk * 64;

        unsigned spdb = (unsigned)__cvta_generic_to_shared(sPD);

        float xa[2][4];
#pragma unroll
        for (int it = 0; it < 2; it++) {
            int slot = tid + it * 512;
            int row = slot >> 4, col = slot & 15;
            cp16(spdb + (row * 64 + col * 4) * 4, g_PpD + row * 64 + col * 4);
        }
        asm volatile("cp.async.commit_group;");
#pragma unroll
        for (int it = 0; it < 2; it++) {
            int slot = tid + it * 512;
            int k = slot & 63, tq = slot >> 6;
            const float* src = x + (T0 + tq * 4) * 1024 + k;
            *(float4*)&sXT[k * 68 + tq * 4] = make_float4(src[0], src[1024], src[2048], src[3072]);
        }
        asm volatile("cp.async.wait_group 0;");
        __syncthreads();

        ull a01[4] = {0,0,0,0}, a23[4] = {0,0,0,0};
        ull s101 = 0, s123 = 0, s201 = 0, s223 = 0;

        for (int c = 0; c < 16; c++) {
            int buf = c & 1;
            if (c < 15) {
#pragma unroll
                for (int it = 0; it < 2; it++) {
                    int slot = tid + it * 512;
                    int row = slot >> 4, col = slot & 15;
                    cp16(spdb + ((buf ^ 1) * 4096 + row * 64 + col * 4) * 4,
                         g_PpD + ((c + 1) * 64 + row) * 64 + col * 4);
                }
                asm volatile("cp.async.commit_group;");
#pragma unroll
                for (int it = 0; it < 2; it++) {
                    int slot = tid + it * 512;
                    int k = slot & 63, tq = slot >> 6;
                    const float* src = x + (T0 + tq * 4) * 1024 + (c + 1) * 64 + k;
                    xa[it][0] = src[0]; xa[it][1] = src[1024];
                    xa[it][2] = src[2048]; xa[it][3] = src[3072];
                }
            }
            const float* xb = sXT + buf * 4352 + tg * 4;
            const float* pb = sPD + buf * 4096 + og * 8;
#pragma unroll
            for (int kl = 0; kl < 16; kl++) {
                int k = ks * 16 + kl;
                ulonglong2 xx = *(const ulonglong2*)(xb + k * 68);
                ulonglong2 q0 = *(const ulonglong2*)(pb + k * 64);
                ulonglong2 q1 = *(const ulonglong2*)(pb + k * 64 + 4);
                FFMA2(a01[0], xx.x, q0.x); FFMA2(a23[0], xx.y, q0.x);
                FFMA2(a01[1], xx.x, q0.y); FFMA2(a23[1], xx.y, q0.y);
                FFMA2(a01[2], xx.x, q1.x); FFMA2(a23[2], xx.y, q1.x);
                FFMA2(a01[3], xx.x, q1.y); FFMA2(a23[3], xx.y, q1.y);
                if (og == 0) {
                    ADD2(s101, xx.x); ADD2(s123, xx.y);
                    FFMA2(s201, xx.x, xx.x); FFMA2(s223, xx.y, xx.y);
                }
            }
            if (c < 15) {
#pragma unroll
                for (int it = 0; it < 2; it++) {
                    int slot = tid + it * 512;
                    int k = slot & 63, tq = slot >> 6;
                    *(float4*)&sXT[(buf ^ 1) * 4352 + k * 68 + tq * 4] =
                        make_float4(xa[it][0], xa[it][1], xa[it][2], xa[it][3]);
                }
                asm volatile("cp.async.wait_group 0;");
            }
            __syncthreads();
        }

        float* Acm = dsm;          // 512 x 16
        float* B   = dsm + 8192;   // 64 x 8
        float* Cc  = dsm + 8704;   // mu[64], rs[64]
        if (ks > 0) {
            ull* d8 = (ull*)&Acm[tid * 16];
#pragma unroll
            for (int i = 0; i < 4; i++) { d8[i] = a01[i]; d8[4 + i] = a23[i]; }
        }
        if (og == 0) {
            ull* sb = (ull*)&B[(ks * 16 + tg) * 8];
            sb[0] = s101; sb[1] = s123; sb[2] = s201; sb[3] = s223;
        }
        __syncthreads();
        if (tid < 64) {
            int tq = tid >> 2, j = tid & 3;
            float s1 = 0.f, s2 = 0.f;
#pragma unroll
            for (int k2 = 0; k2 < 4; k2++) {
                const float* bb = &B[(k2 * 16 + tq) * 8];
                s1 += bb[j];
                s2 += bb[4 + j];
            }
            float mu = s1 * (1.f / 1024.f);
            float var = s2 * (1.f / 1024.f) - mu * mu;
            Cc[tid] = mu;
            Cc[64 + tid] = rsqrtf(var + 1e-5f);
        }
        if (ks == 0) {
#pragma unroll
            for (int k2 = 1; k2 < 4; k2++) {
                const ull* src = (const ull*)&Acm[(tid + k2 * 16) * 16];
#pragma unroll
                for (int i = 0; i < 4; i++) { ADD2(a01[i], src[i]); ADD2(a23[i], src[4 + i]); }
            }
        }
        __syncthreads();
        if (ks == 0) {
            float mu[4], rs[4];
#pragma unroll
            for (int j = 0; j < 4; j++) { mu[j] = Cc[tg * 4 + j]; rs[j] = Cc[64 + tg * 4 + j]; }
            int b = T0 >> 12;
            int s0 = (T0 & 4095) + tg * 4;
#pragma unroll
            for (int i = 0; i < 4; i++) {
                int o = og * 4 + i;
                float k1v = g_k1[o], k2v = g_k2[o];
                float v[4];
                unpk(v[0], v[1], a01[i]);
                unpk(v[2], v[3], a23[i]);
#pragma unroll
                for (int j = 0; j < 4; j++) {
                    v[j] = rs[j] * v[j] - mu[j] * rs[j] * k1v + k2v;
                    if (o < 16) v[j] = 1.f / (1.f + __expf(-v[j]));
                }
                *(float4*)&g_au[(b * 32 + o) * 4096 + s0] = make_float4(v[0], v[1], v[2], v[3]);
            }
        }
    }
    gsync();

    // ================= P2: scan (blocks 0..31) =================
    if (blk < 32) {
        __shared__ float wA[16], wU[16], pU[16];
        int bn = blk;
        int b = bn >> 4, n = bn & 15;
        const float* ap = g_au + (b * 32 + n) * 4096;
        const float* up = g_au + (b * 32 + 16 + n) * 4096;

        float a[8], u[8];
        const float4* a4 = (const float4*)(ap + tid * 8);
        const float4* u4 = (const float4*)(up + tid * 8);
#pragma unroll
        for (int q = 0; q < 2; q++) {
            float4 av = a4[q], uv = u4[q];
            a[q*4+0] = av.x; a[q*4+1] = av.y; a[q*4+2] = av.z; a[q*4+3] = av.w;
            u[q*4+0] = uv.x; u[q*4+1] = uv.y; u[q*4+2] = uv.z; u[q*4+3] = uv.w;
        }
        float Aloc = 1.f, Uloc = 0.f;
#pragma unroll
        for (int i = 0; i < 8; i++) { Uloc = Uloc * a[i] + u[i]; Aloc *= a[i]; }

        float Ai = Aloc, Ui = Uloc;
#pragma unroll
        for (int off = 1; off < 32; off <<= 1) {
            float Ap = __shfl_up_sync(0xffffffffu, Ai, off);
            float Up = __shfl_up_sync(0xffffffffu, Ui, off);
            if (lane >= off) { Ui = Up * Ai + Ui; Ai = Ap * Ai; }
        }
        if (lane == 31) { wA[wid] = Ai; wU[wid] = Ui; }
        __syncthreads();
        if (tid == 0) {
            float Uc = 0.f;
#pragma unroll
            for (int j = 0; j < 16; j++) {
                pU[j] = Uc;
                Uc = Uc * wA[j] + wU[j];
            }
        }
        __syncthreads();
        float eA = __shfl_up_sync(0xffffffffu, Ai, 1);
        float eU = __shfl_up_sync(0xffffffffu, Ui, 1);
        if (lane == 0) { eA = 1.f; eU = 0.f; }
        float s = pU[wid] * eA + eU;

        float o8[8];
#pragma unroll
        for (int i = 0; i < 8; i++) { s = a[i] * s + u[i]; o8[i] = s; }
        float4* dst = (float4*)(g_states + bn * 4096 + tid * 8);
#pragma unroll
        for (int q = 0; q < 2; q++)
            dst[q] = make_float4(o8[q*4+0], o8[q*4+1], o8[q*4+2], o8[q*4+3]);
    }
    gsync();

    // ================= P3: out =================
    {
        float* sST = dsm;   // 64 tokens x 17
        int T0 = blk * 64;
        int b = T0 >> 12, s0 = T0 & 4095;
#pragma unroll
        for (int it = 0; it < 2; it++) {
            int idx = tid + it * 512;
            int soff = idx & 63, n = idx >> 6;
            sST[soff * 17 + n] = g_states[(b * 16 + n) * 4096 + s0 + soff];
        }
        int dq = tid & 255;
        int th = tid >> 8;
        ull m01[16], m23[16];
#pragma unroll
        for (int n = 0; n < 16; n++) {
            ulonglong2 mm = *(const ulonglong2*)(g_MT + n * 1024 + dq * 4);
            m01[n] = mm.x; m23[n] = mm.y;
        }
        ulonglong2 bov = *(const ulonglong2*)(bo + dq * 4);
        __syncthreads();

        for (int tl = 0; tl < 32; tl++) {
            int t = th * 32 + tl;
            ulonglong2 xv = *(const ulonglong2*)(x + (T0 + t) * 1024 + dq * 4);
            ull r01, r23;
            asm("add.rn.f32x2 %0, %1, %2;" : "=l"(r01) : "l"(xv.x), "l"(bov.x));
            asm("add.rn.f32x2 %0, %1, %2;" : "=l"(r23) : "l"(xv.y), "l"(bov.y));
#pragma unroll
            for (int n = 0; n < 16; n++) {
                ull sv = dup_f(sST[t * 17 + n]);
                FFMA2(r01, sv, m01[n]);
                FFMA2(r23, sv, m23[n]);
            }
            ulonglong2 res; res.x = r01; res.y = r23;
            *(ulonglong2*)(out + (T0 + t) * 1024 + dq * 4) = res;
        }
    }
}

// ---------------- launch ----------------
extern "C" void kernel_launch(void* const* d_in, const int* in_sizes, int n_in,
                              void* d_out, int out_size) {
    const float* x    = (const float*)d_in[0];
    const float* nw   = (const float*)d_in[1];
    const float* nb   = (const float*)d_in[2];
    const float* Win  = (const float*)d_in[3];
    const float* b_in = (const float*)d_in[4];
    const float* A    = (const float*)d_in[5];
    const float* Bs   = (const float*)d_in[6];
    const float* C    = (const float*)d_in[7];
    const float* Wout = (const float*)d_in[8];
    const float* bo   = (const float*)d_in[9];
    float* out = (float*)d_out;

    cudaFuncSetAttribute(k_main, cudaFuncAttributeMaxDynamicSharedMemorySize, 69632);

    k_main<<<GRID, NT, 67584>>>(x, nw, nb, Win, b_in, A, Bs, C, Wout, bo, out);
}

// round 11
// speedup vs baseline: 1.1950x; 1.1950x over previous
#include <cuda_runtime.h>
#include <math.h>

#define GRID 128
#define NT 512

// ---------------- scratch ----------------
__device__ __align__(16) float g_Ppart[32 * 32 * 1024]; // [chunk(32)][o][d]
__device__ __align__(16) float g_MTp[8 * 16 * 1024];    // [oct(8)][n][d]
__device__ __align__(16) float g_PpD[1024 * 64];        // [k][{o,o} duplicated]
__device__ __align__(16) float g_MT[16 * 1024];         // [n][d]
__device__ float g_c[32];
__device__ float g_k1[32];
__device__ float g_k2[32];
__device__ __align__(16) float g_au[2 * 32 * 4096];     // [b][o][s]
__device__ __align__(16) float g_states[2 * 16 * 4096]; // [b*16+n][s]
__device__ int g_cnt;                                   // barrier (monotonic)

typedef unsigned long long ull;
__device__ __forceinline__ ull dup_f(float v) {
    ull r; asm("mov.b64 %0, {%1, %1};" : "=l"(r) : "f"(v)); return r;
}
#define FFMA2(acc, a, b) asm("fma.rn.f32x2 %0, %1, %2, %0;" : "+l"(acc) : "l"(a), "l"(b))
#define ADD2(acc, a)     asm("add.rn.f32x2 %0, %0, %1;" : "+l"(acc) : "l"(a))
__device__ __forceinline__ void unpk(float& lo, float& hi, ull v) {
    asm("mov.b64 {%0, %1}, %2;" : "=f"(lo), "=f"(hi) : "l"(v));
}
__device__ __forceinline__ void cp16(unsigned int dst, const void* src) {
    asm volatile("cp.async.ca.shared.global [%0], [%1], 16;" :: "r"(dst), "l"(src));
}

// grid-wide barrier: monotonic counter, replay-safe
__device__ __forceinline__ void gsync() {
    __syncthreads();
    if (threadIdx.x == 0) {
        __threadfence();
        int arrival = atomicAdd(&g_cnt, 1);
        int target = (arrival / GRID + 1) * GRID;
        while (*((volatile int*)&g_cnt) < target) { }
        __threadfence();
    }
    __syncthreads();
}

// ---------------- single fused kernel ----------------
__global__ void __launch_bounds__(NT) k_main(const float* __restrict__ x,
                                             const float* __restrict__ nw,
                                             const float* __restrict__ nb,
                                             const float* __restrict__ Win,
                                             const float* __restrict__ b_in,
                                             const float* __restrict__ A,
                                             const float* __restrict__ Bs,
                                             const float* __restrict__ C,
                                             const float* __restrict__ Wout,
                                             const float* __restrict__ bo,
                                             float* __restrict__ out) {
    extern __shared__ float dsm[];   // 16896 floats = 67584 B
    int tid = threadIdx.x;
    int blk = blockIdx.x;
    int lane = tid & 31, wid = tid >> 5;

    // ================= P-1: prologue, ALL 128 blocks busy (256 units of 256 thr) =================
    if (blk < 64) {
        // --- P partials: units 0..127 ; unit covers d-tile(256) x e-chunk(64) ---
        ull* sAB2 = (ull*)dsm + (tid >> 8) * 2048;  // 16KB per unit
        int t2 = tid & 255;
        int unit = blk * 2 + (tid >> 8);
        int dt = unit >> 5;          // 0..3  (d-tile of 256)
        int chunk = unit & 31;       // 0..31 (e-chunk of 64)
        int e0 = chunk * 64;
        for (int i = t2; i < 64 * 16; i += 256) {
            int el = i >> 4, n = i & 15;
            sAB2[el * 32 + n]      = dup_f(A [(e0 + el) * 16 + n]);
            sAB2[el * 32 + 16 + n] = dup_f(Bs[(e0 + el) * 16 + n]);
        }
        __syncthreads();
        int dp = t2 >> 1, oh = t2 & 1;
        int d = dt * 256 + dp * 2;
        ull acc[16];
#pragma unroll
        for (int o = 0; o < 16; o++) acc[o] = 0ull;
#pragma unroll 4
        for (int el = 0; el < 64; el++) {
            ull w01 = *(const ull*)(Win + (e0 + el) * 1024 + d);
            const ull* base = sAB2 + el * 32 + oh * 16;
#pragma unroll
            for (int o = 0; o < 16; o++) FFMA2(acc[o], w01, base[o]);
        }
#pragma unroll
        for (int o = 0; o < 16; o++) {
            int oi = oh * 16 + o;
            *(ull*)(g_Ppart + (chunk * 32 + oi) * 1024 + d) = acc[o];
        }
    } else {
        // --- MT partials: units 0..127 ; unit covers row-tile(64) x e-octant(256) ---
        float* sC = dsm + (tid >> 8) * 2048;   // 8KB per unit
        int t2 = tid & 255;
        int unit = (blk - 64) * 2 + (tid >> 8);
        int tile = unit >> 3;        // 0..15 (64 Wout rows)
        int oct = unit & 7;          // 0..7  (256 e)
        int row = tile * 64 + (t2 >> 2);
        int nq = t2 & 3;
        ull acc0 = 0ull, acc1 = 0ull;
        for (int c = 0; c < 2; c++) {
            int e0 = oct * 256 + c * 128;
            __syncthreads();
            for (int i = t2; i < 512; i += 256)
                ((float4*)sC)[i] = ((const float4*)(C + e0 * 16))[i];
            __syncthreads();
            const float* wrow = Wout + row * 2048 + e0;
#pragma unroll 8
            for (int g = 0; g < 32; g++) {
                float4 w4 = *(const float4*)(wrow + g * 4);
#pragma unroll
                for (int j = 0; j < 4; j++) {
                    float wv = (j == 0) ? w4.x : (j == 1) ? w4.y : (j == 2) ? w4.z : w4.w;
                    ull wd = dup_f(wv);
                    ulonglong2 cp = *(const ulonglong2*)(sC + (g * 4 + j) * 16 + nq * 4);
                    FFMA2(acc0, wd, cp.x);
                    FFMA2(acc1, wd, cp.y);
                }
            }
        }
        float a[4];
        unpk(a[0], a[1], acc0);
        unpk(a[2], a[3], acc1);
#pragma unroll
        for (int i = 0; i < 4; i++) {
            int n = nq * 4 + i;
            g_MTp[(oct * 16 + n) * 1024 + row] = a[i];
        }
    }
    gsync();

    // ================= P0: fold (+ bias c on block 64) =================
    if (blk < 32) {
        __shared__ float sred[32];
        int o = blk;
        float s1 = 0.f, s2 = 0.f;
#pragma unroll
        for (int h = 0; h < 2; h++) {
            int d = tid + h * 512;
            float p = 0.f;
#pragma unroll
            for (int c = 0; c < 32; c++) p += g_Ppart[(c * 32 + o) * 1024 + d];
            float pp = nw[d] * p;
            s1 += pp;
            s2 += nb[d] * p;
            *(float2*)&g_PpD[d * 64 + o * 2] = make_float2(pp, pp);
        }
#pragma unroll
        for (int off = 16; off; off >>= 1) {
            s1 += __shfl_down_sync(0xffffffffu, s1, off);
            s2 += __shfl_down_sync(0xffffffffu, s2, off);
        }
        if (lane == 0) { sred[wid] = s1; sred[16 + wid] = s2; }
        __syncthreads();
        if (tid == 0) {
            float S1 = 0.f, S2 = 0.f;
#pragma unroll
            for (int j = 0; j < 16; j++) { S1 += sred[j]; S2 += sred[16 + j]; }
            g_k1[o] = S1;
            g_k2[o] = S2;
        }
    } else if (blk < 64) {
        int base = (blk - 32) * 512 + tid;
        int d = base & 1023, n = base >> 10;
        float s = 0.f;
#pragma unroll
        for (int q = 0; q < 8; q++) s += g_MTp[(q * 16 + n) * 1024 + d];
        g_MT[n * 1024 + d] = s;
    } else if (blk == 64) {
        // bias c = b_in @ {A|B}: two 256-thread units
        float* red = dsm + (tid >> 8) * 128;
        int t2 = tid & 255;
        int half = tid >> 8;
        int l2 = t2 & 31, w2 = t2 >> 5;
        const float* G = half ? Bs : A;
        float acc[16];
#pragma unroll
        for (int n = 0; n < 16; n++) acc[n] = 0.f;
        for (int e = t2; e < 2048; e += 256) {
            float bv = b_in[e];
            const float4* g4 = (const float4*)(G + e * 16);
            float4 c0 = g4[0], c1 = g4[1], c2 = g4[2], c3 = g4[3];
            acc[0] += bv * c0.x; acc[1] += bv * c0.y; acc[2] += bv * c0.z; acc[3] += bv * c0.w;
            acc[4] += bv * c1.x; acc[5] += bv * c1.y; acc[6] += bv * c1.z; acc[7] += bv * c1.w;
            acc[8] += bv * c2.x; acc[9] += bv * c2.y; acc[10]+= bv * c2.z; acc[11]+= bv * c2.w;
            acc[12]+= bv * c3.x; acc[13]+= bv * c3.y; acc[14]+= bv * c3.z; acc[15]+= bv * c3.w;
        }
#pragma unroll
        for (int off = 16; off; off >>= 1)
#pragma unroll
            for (int n = 0; n < 16; n++) acc[n] += __shfl_down_sync(0xffffffffu, acc[n], off);
        if (l2 == 0) {
#pragma unroll
            for (int n = 0; n < 16; n++) red[w2 * 16 + n] = acc[n];
        }
        __syncthreads();
        if (t2 < 16) {
            float s = 0.f;
#pragma unroll
            for (int j = 0; j < 8; j++) s += red[j * 16 + t2];
            g_c[half * 16 + t2] = s;
        }
    }
    gsync();

    // ================= P1: LN + projection =================
    {
        float* sXT = dsm;          // 2 x (64 k x 68) = 8704 floats
        float* sPD = dsm + 8704;   // 2 x (64 k x 64) = 8192 floats
        int tg = tid & 15;         // token quad
        int ks = (tid >> 4) & 3;   // k-split
        int og = tid >> 6;         // output quad (warp-uniform)
        int T0 = blk * 64;

        unsigned spdb = (unsigned)__cvta_generic_to_shared(sPD);

        float xa[2][4];
#pragma unroll
        for (int it = 0; it < 2; it++) {
            int slot = tid + it * 512;
            int row = slot >> 4, col = slot & 15;
            cp16(spdb + (row * 64 + col * 4) * 4, g_PpD + row * 64 + col * 4);
        }
        asm volatile("cp.async.commit_group;");
#pragma unroll
        for (int it = 0; it < 2; it++) {
            int slot = tid + it * 512;
            int k = slot & 63, tq = slot >> 6;
            const float* src = x + (T0 + tq * 4) * 1024 + k;
            *(float4*)&sXT[k * 68 + tq * 4] = make_float4(src[0], src[1024], src[2048], src[3072]);
        }
        asm volatile("cp.async.wait_group 0;");
        __syncthreads();

        ull a01[4] = {0,0,0,0}, a23[4] = {0,0,0,0};
        ull s101 = 0, s123 = 0, s201 = 0, s223 = 0;

        for (int c = 0; c < 16; c++) {
            int buf = c & 1;
            if (c < 15) {
#pragma unroll
                for (int it = 0; it < 2; it++) {
                    int slot = tid + it * 512;
                    int row = slot >> 4, col = slot & 15;
                    cp16(spdb + ((buf ^ 1) * 4096 + row * 64 + col * 4) * 4,
                         g_PpD + ((c + 1) * 64 + row) * 64 + col * 4);
                }
                asm volatile("cp.async.commit_group;");
#pragma unroll
                for (int it = 0; it < 2; it++) {
                    int slot = tid + it * 512;
                    int k = slot & 63, tq = slot >> 6;
                    const float* src = x + (T0 + tq * 4) * 1024 + (c + 1) * 64 + k;
                    xa[it][0] = src[0]; xa[it][1] = src[1024];
                    xa[it][2] = src[2048]; xa[it][3] = src[3072];
                }
            }
            const float* xb = sXT + buf * 4352 + tg * 4;
            const float* pb = sPD + buf * 4096 + og * 8;
#pragma unroll
            for (int kl = 0; kl < 16; kl++) {
                int k = ks * 16 + kl;
                ulonglong2 xx = *(const ulonglong2*)(xb + k * 68);
                ulonglong2 q0 = *(const ulonglong2*)(pb + k * 64);
                ulonglong2 q1 = *(const ulonglong2*)(pb + k * 64 + 4);
                FFMA2(a01[0], xx.x, q0.x); FFMA2(a23[0], xx.y, q0.x);
                FFMA2(a01[1], xx.x, q0.y); FFMA2(a23[1], xx.y, q0.y);
                FFMA2(a01[2], xx.x, q1.x); FFMA2(a23[2], xx.y, q1.x);
                FFMA2(a01[3], xx.x, q1.y); FFMA2(a23[3], xx.y, q1.y);
                if (og == 0) {
                    ADD2(s101, xx.x); ADD2(s123, xx.y);
                    FFMA2(s201, xx.x, xx.x); FFMA2(s223, xx.y, xx.y);
                }
            }
            if (c < 15) {
#pragma unroll
                for (int it = 0; it < 2; it++) {
                    int slot = tid + it * 512;
                    int k = slot & 63, tq = slot >> 6;
                    *(float4*)&sXT[(buf ^ 1) * 4352 + k * 68 + tq * 4] =
                        make_float4(xa[it][0], xa[it][1], xa[it][2], xa[it][3]);
                }
                asm volatile("cp.async.wait_group 0;");
            }
            __syncthreads();
        }

        float* Acm = dsm;          // 512 x 16
        float* B   = dsm + 8192;   // 64 x 8
        float* Cc  = dsm + 8704;   // mu[64], rs[64]
        if (ks > 0) {
            ull* d8 = (ull*)&Acm[tid * 16];
#pragma unroll
            for (int i = 0; i < 4; i++) { d8[i] = a01[i]; d8[4 + i] = a23[i]; }
        }
        if (og == 0) {
            ull* sb = (ull*)&B[(ks * 16 + tg) * 8];
            sb[0] = s101; sb[1] = s123; sb[2] = s201; sb[3] = s223;
        }
        __syncthreads();
        if (tid < 64) {
            int tq = tid >> 2, j = tid & 3;
            float s1 = 0.f, s2 = 0.f;
#pragma unroll
            for (int k2 = 0; k2 < 4; k2++) {
                const float* bb = &B[(k2 * 16 + tq) * 8];
                s1 += bb[j];
                s2 += bb[4 + j];
            }
            float mu = s1 * (1.f / 1024.f);
            float var = s2 * (1.f / 1024.f) - mu * mu;
            Cc[tid] = mu;
            Cc[64 + tid] = rsqrtf(var + 1e-5f);
        }
        if (ks == 0) {
#pragma unroll
            for (int k2 = 1; k2 < 4; k2++) {
                const ull* src = (const ull*)&Acm[(tid + k2 * 16) * 16];
#pragma unroll
                for (int i = 0; i < 4; i++) { ADD2(a01[i], src[i]); ADD2(a23[i], src[4 + i]); }
            }
        }
        __syncthreads();
        if (ks == 0) {
            float mu[4], rs[4];
#pragma unroll
            for (int j = 0; j < 4; j++) { mu[j] = Cc[tg * 4 + j]; rs[j] = Cc[64 + tg * 4 + j]; }
            int b = T0 >> 12;
            int s0 = (T0 & 4095) + tg * 4;
#pragma unroll
            for (int i = 0; i < 4; i++) {
                int o = og * 4 + i;
                float k1v = g_k1[o];
                float k2v = g_k2[o] + g_c[o];
                float v[4];
                unpk(v[0], v[1], a01[i]);
                unpk(v[2], v[3], a23[i]);
#pragma unroll
                for (int j = 0; j < 4; j++) {
                    v[j] = rs[j] * v[j] - mu[j] * rs[j] * k1v + k2v;
                    if (o < 16) v[j] = 1.f / (1.f + __expf(-v[j]));
                }
                *(float4*)&g_au[(b * 32 + o) * 4096 + s0] = make_float4(v[0], v[1], v[2], v[3]);
            }
        }
    }
    gsync();

    // ================= P2: scan (blocks 0..31) =================
    if (blk < 32) {
        __shared__ float wA[16], wU[16], pU[16];
        int bn = blk;
        int b = bn >> 4, n = bn & 15;
        const float* ap = g_au + (b * 32 + n) * 4096;
        const float* up = g_au + (b * 32 + 16 + n) * 4096;

        float a[8], u[8];
        const float4* a4 = (const float4*)(ap + tid * 8);
        const float4* u4 = (const float4*)(up + tid * 8);
#pragma unroll
        for (int q = 0; q < 2; q++) {
            float4 av = a4[q], uv = u4[q];
            a[q*4+0] = av.x; a[q*4+1] = av.y; a[q*4+2] = av.z; a[q*4+3] = av.w;
            u[q*4+0] = uv.x; u[q*4+1] = uv.y; u[q*4+2] = uv.z; u[q*4+3] = uv.w;
        }
        float Aloc = 1.f, Uloc = 0.f;
#pragma unroll
        for (int i = 0; i < 8; i++) { Uloc = Uloc * a[i] + u[i]; Aloc *= a[i]; }

        float Ai = Aloc, Ui = Uloc;
#pragma unroll
        for (int off = 1; off < 32; off <<= 1) {
            float Ap = __shfl_up_sync(0xffffffffu, Ai, off);
            float Up = __shfl_up_sync(0xffffffffu, Ui, off);
            if (lane >= off) { Ui = Up * Ai + Ui; Ai = Ap * Ai; }
        }
        if (lane == 31) { wA[wid] = Ai; wU[wid] = Ui; }
        __syncthreads();
        if (tid == 0) {
            float Uc = 0.f;
#pragma unroll
            for (int j = 0; j < 16; j++) {
                pU[j] = Uc;
                Uc = Uc * wA[j] + wU[j];
            }
        }
        __syncthreads();
        float eA = __shfl_up_sync(0xffffffffu, Ai, 1);
        float eU = __shfl_up_sync(0xffffffffu, Ui, 1);
        if (lane == 0) { eA = 1.f; eU = 0.f; }
        float s = pU[wid] * eA + eU;

        float o8[8];
#pragma unroll
        for (int i = 0; i < 8; i++) { s = a[i] * s + u[i]; o8[i] = s; }
        float4* dst = (float4*)(g_states + bn * 4096 + tid * 8);
#pragma unroll
        for (int q = 0; q < 2; q++)
            dst[q] = make_float4(o8[q*4+0], o8[q*4+1], o8[q*4+2], o8[q*4+3]);
    }
    gsync();

    // ================= P3: out =================
    {
        float* sST = dsm;   // 64 tokens x 17
        int T0 = blk * 64;
        int b = T0 >> 12, s0 = T0 & 4095;
#pragma unroll
        for (int it = 0; it < 2; it++) {
            int idx = tid + it * 512;
            int soff = idx & 63, n = idx >> 6;
            sST[soff * 17 + n] = g_states[(b * 16 + n) * 4096 + s0 + soff];
        }
        int dq = tid & 255;
        int th = tid >> 8;
        ull m01[16], m23[16];
#pragma unroll
        for (int n = 0; n < 16; n++) {
            ulonglong2 mm = *(const ulonglong2*)(g_MT + n * 1024 + dq * 4);
            m01[n] = mm.x; m23[n] = mm.y;
        }
        ulonglong2 bov = *(const ulonglong2*)(bo + dq * 4);
        __syncthreads();

        for (int tl = 0; tl < 32; tl++) {
            int t = th * 32 + tl;
            ulonglong2 xv = *(const ulonglong2*)(x + (T0 + t) * 1024 + dq * 4);
            ull r01, r23;
            asm("add.rn.f32x2 %0, %1, %2;" : "=l"(r01) : "l"(xv.x), "l"(bov.x));
            asm("add.rn.f32x2 %0, %1, %2;" : "=l"(r23) : "l"(xv.y), "l"(bov.y));
#pragma unroll
            for (int n = 0; n < 16; n++) {
                ull sv = dup_f(sST[t * 17 + n]);
                FFMA2(r01, sv, m01[n]);
                FFMA2(r23, sv, m23[n]);
            }
            ulonglong2 res; res.x = r01; res.y = r23;
            *(ulonglong2*)(out + (T0 + t) * 1024 + dq * 4) = res;
        }
    }
}

// ---------------- launch ----------------
extern "C" void kernel_launch(void* const* d_in, const int* in_sizes, int n_in,
                              void* d_out, int out_size) {
    const float* x    = (const float*)d_in[0];
    const float* nw   = (const float*)d_in[1];
    const float* nb   = (const float*)d_in[2];
    const float* Win  = (const float*)d_in[3];
    const float* b_in = (const float*)d_in[4];
    const float* A    = (const float*)d_in[5];
    const float* Bs   = (const float*)d_in[6];
    const float* C    = (const float*)d_in[7];
    const float* Wout = (const float*)d_in[8];
    const float* bo   = (const float*)d_in[9];
    float* out = (float*)d_out;

    cudaFuncSetAttribute(k_main, cudaFuncAttributeMaxDynamicSharedMemorySize, 69632);

    k_main<<<GRID, NT, 67584>>>(x, nw, nb, Win, b_in, A, Bs, C, Wout, bo, out);
}

// round 12
// speedup vs baseline: 1.3242x; 1.1081x over previous
#include <cuda_runtime.h>
#include <math.h>

#define GRID 128
#define NT 512

// ---------------- scratch ----------------
__device__ __align__(16) float g_Ppart[64 * 32 * 1024]; // [chunk(64)][o][d]  (L2-resident)
__device__ __align__(16) float g_MTp[8 * 16 * 1024];    // [oct(8)][n][d]
__device__ __align__(16) float g_Pp[1024 * 32];         // [k][o] plain
__device__ __align__(16) float g_MT[16 * 1024];         // [n][d]
__device__ float g_c[32];
__device__ float g_k1[32];
__device__ float g_k2[32];
__device__ __align__(16) float g_au[2 * 32 * 4096];     // [b][o][s]
__device__ __align__(16) float g_states[2 * 16 * 4096]; // [b*16+n][s]
__device__ int g_cnt;                                   // barrier (monotonic)

typedef unsigned long long ull;
__device__ __forceinline__ ull dup_f(float v) {
    ull r; asm("mov.b64 %0, {%1, %1};" : "=l"(r) : "f"(v)); return r;
}
#define FFMA2(acc, a, b) asm("fma.rn.f32x2 %0, %1, %2, %0;" : "+l"(acc) : "l"(a), "l"(b))
#define ADD2(acc, a)     asm("add.rn.f32x2 %0, %0, %1;" : "+l"(acc) : "l"(a))
__device__ __forceinline__ void unpk(float& lo, float& hi, ull v) {
    asm("mov.b64 {%0, %1}, %2;" : "=f"(lo), "=f"(hi) : "l"(v));
}
__device__ __forceinline__ void cp16(unsigned int dst, const void* src) {
    asm volatile("cp.async.ca.shared.global [%0], [%1], 16;" :: "r"(dst), "l"(src));
}

// grid-wide barrier: monotonic counter, replay-safe
__device__ __forceinline__ void gsync() {
    __syncthreads();
    if (threadIdx.x == 0) {
        __threadfence();
        int arrival = atomicAdd(&g_cnt, 1);
        int target = (arrival / GRID + 1) * GRID;
        while (*((volatile int*)&g_cnt) < target) { }
        __threadfence();
    }
    __syncthreads();
}

// ---------------- single fused kernel ----------------
__global__ void __launch_bounds__(NT) k_main(const float* __restrict__ x,
                                             const float* __restrict__ nw,
                                             const float* __restrict__ nb,
                                             const float* __restrict__ Win,
                                             const float* __restrict__ b_in,
                                             const float* __restrict__ A,
                                             const float* __restrict__ Bs,
                                             const float* __restrict__ C,
                                             const float* __restrict__ Wout,
                                             const float* __restrict__ bo,
                                             float* __restrict__ out) {
    extern __shared__ float dsm[];   // 16896 floats = 67584 B
    int tid = threadIdx.x;
    int blk = blockIdx.x;
    int lane = tid & 31, wid = tid >> 5;

    // ================= Phase A: P split-K partials, ALL 256 units =================
    // unit = (dt 0..3) x (chunk 0..63 of 32 e) ; o-half split inside by t2&1
    {
        ull* sAB2 = (ull*)dsm + (tid >> 8) * 1024;  // 8KB per unit
        int t2 = tid & 255;
        int unit = blk * 2 + (tid >> 8);
        int dt = unit >> 6;          // 0..3  (d-tile of 256)
        int chunk = unit & 63;       // 0..63 (e-chunk of 32)
        int e0 = chunk * 32;
        for (int i = t2; i < 512; i += 256) {
            int el = i >> 4, n = i & 15;
            sAB2[el * 32 + n]      = dup_f(A [(e0 + el) * 16 + n]);
            sAB2[el * 32 + 16 + n] = dup_f(Bs[(e0 + el) * 16 + n]);
        }
        __syncthreads();
        int dp = t2 >> 1, oh = t2 & 1;
        int d = dt * 256 + dp * 2;
        ull acc[16];
#pragma unroll
        for (int o = 0; o < 16; o++) acc[o] = 0ull;
#pragma unroll 4
        for (int el = 0; el < 32; el++) {
            ull w01 = *(const ull*)(Win + (e0 + el) * 1024 + d);
            const ull* base = sAB2 + el * 32 + oh * 16;
#pragma unroll
            for (int o = 0; o < 16; o++) FFMA2(acc[o], w01, base[o]);
        }
#pragma unroll
        for (int o = 0; o < 16; o++)
            *(ull*)(g_Ppart + (chunk * 32 + oh * 16 + o) * 1024 + d) = acc[o];
    }
    gsync();

    // ================= Phase B: fold-P (0-31) | bias (32) | MT partials (33-96) =================
    if (blk < 32) {
        __shared__ float sred[32];
        int o = blk;
        float s1 = 0.f, s2 = 0.f;
#pragma unroll
        for (int h = 0; h < 2; h++) {
            int d = tid + h * 512;
            float p = 0.f;
#pragma unroll 16
            for (int c = 0; c < 64; c++) p += g_Ppart[(c * 32 + o) * 1024 + d];
            float pp = nw[d] * p;
            s1 += pp;
            s2 += nb[d] * p;
            g_Pp[d * 32 + o] = pp;
        }
#pragma unroll
        for (int off = 16; off; off >>= 1) {
            s1 += __shfl_down_sync(0xffffffffu, s1, off);
            s2 += __shfl_down_sync(0xffffffffu, s2, off);
        }
        if (lane == 0) { sred[wid] = s1; sred[16 + wid] = s2; }
        __syncthreads();
        if (tid == 0) {
            float S1 = 0.f, S2 = 0.f;
#pragma unroll
            for (int j = 0; j < 16; j++) { S1 += sred[j]; S2 += sred[16 + j]; }
            g_k1[blk] = S1;
            g_k2[blk] = S2;
        }
    } else if (blk == 32) {
        // bias c = b_in @ {A|B}: two 256-thread units
        float* red = dsm + (tid >> 8) * 128;
        int t2 = tid & 255;
        int half = tid >> 8;
        int l2 = t2 & 31, w2 = t2 >> 5;
        const float* G = half ? Bs : A;
        float acc[16];
#pragma unroll
        for (int n = 0; n < 16; n++) acc[n] = 0.f;
        for (int e = t2; e < 2048; e += 256) {
            float bv = b_in[e];
            const float4* g4 = (const float4*)(G + e * 16);
            float4 c0 = g4[0], c1 = g4[1], c2 = g4[2], c3 = g4[3];
            acc[0] += bv * c0.x; acc[1] += bv * c0.y; acc[2] += bv * c0.z; acc[3] += bv * c0.w;
            acc[4] += bv * c1.x; acc[5] += bv * c1.y; acc[6] += bv * c1.z; acc[7] += bv * c1.w;
            acc[8] += bv * c2.x; acc[9] += bv * c2.y; acc[10]+= bv * c2.z; acc[11]+= bv * c2.w;
            acc[12]+= bv * c3.x; acc[13]+= bv * c3.y; acc[14]+= bv * c3.z; acc[15]+= bv * c3.w;
        }
#pragma unroll
        for (int off = 16; off; off >>= 1)
#pragma unroll
            for (int n = 0; n < 16; n++) acc[n] += __shfl_down_sync(0xffffffffu, acc[n], off);
        if (l2 == 0) {
#pragma unroll
            for (int n = 0; n < 16; n++) red[w2 * 16 + n] = acc[n];
        }
        __syncthreads();
        if (t2 < 16) {
            float s = 0.f;
#pragma unroll
            for (int j = 0; j < 8; j++) s += red[j * 16 + t2];
            g_c[half * 16 + t2] = s;
        }
    } else if (blk <= 96) {
        // MT partials: 128 units ; unit covers row-tile(64) x e-octant(256)
        float* sC = dsm + (tid >> 8) * 2048;   // 8KB per unit
        int t2 = tid & 255;
        int unit = (blk - 33) * 2 + (tid >> 8);
        int tile = unit >> 3;        // 0..15 (64 Wout rows)
        int oct = unit & 7;          // 0..7  (256 e)
        int row = tile * 64 + (t2 >> 2);
        int nq = t2 & 3;
        ull acc0 = 0ull, acc1 = 0ull;
        for (int c = 0; c < 2; c++) {
            int e0 = oct * 256 + c * 128;
            __syncthreads();
            for (int i = t2; i < 512; i += 256)
                ((float4*)sC)[i] = ((const float4*)(C + e0 * 16))[i];
            __syncthreads();
            const float* wrow = Wout + row * 2048 + e0;
#pragma unroll 8
            for (int g = 0; g < 32; g++) {
                float4 w4 = *(const float4*)(wrow + g * 4);
#pragma unroll
                for (int j = 0; j < 4; j++) {
                    float wv = (j == 0) ? w4.x : (j == 1) ? w4.y : (j == 2) ? w4.z : w4.w;
                    ull wd = dup_f(wv);
                    ulonglong2 cp = *(const ulonglong2*)(sC + (g * 4 + j) * 16 + nq * 4);
                    FFMA2(acc0, wd, cp.x);
                    FFMA2(acc1, wd, cp.y);
                }
            }
        }
        float a[4];
        unpk(a[0], a[1], acc0);
        unpk(a[2], a[3], acc1);
#pragma unroll
        for (int i = 0; i < 4; i++) {
            int n = nq * 4 + i;
            g_MTp[(oct * 16 + n) * 1024 + row] = a[i];
        }
    }
    gsync();

    // ================= Phase C: LN + projection (output-pair FFMA2, plain P) =================
    {
        float* sXT = dsm;          // 2 x (64 k x 68) = 8704 floats
        float* sP  = dsm + 8704;   // 2 x (64 k x 32) = 4096 floats
        int tg = tid & 15;         // token quad
        int ks = (tid >> 4) & 3;   // k-split
        int og = tid >> 6;         // output quad (warp-uniform)
        int T0 = blk * 64;

        unsigned spb = (unsigned)__cvta_generic_to_shared(sP);

        // prologue: chunk 0
        {
            int row = tid >> 3, col = tid & 7;   // 64 rows x 8 float4 (tid<512 covers all)
            cp16(spb + (row * 32 + col * 4) * 4, g_Pp + row * 32 + col * 4);
            asm volatile("cp.async.commit_group;");
#pragma unroll
            for (int it = 0; it < 2; it++) {
                int slot = tid + it * 512;
                int k = slot & 63, tq = slot >> 6;
                const float* src = x + (T0 + tq * 4) * 1024 + k;
                *(float4*)&sXT[k * 68 + tq * 4] = make_float4(src[0], src[1024], src[2048], src[3072]);
            }
            asm volatile("cp.async.wait_group 0;");
            __syncthreads();
        }

        ull acc[8] = {0,0,0,0,0,0,0,0};   // [token j][o-pair h] = acc[j*2+h]
        float s1[4] = {0,0,0,0}, s2[4] = {0,0,0,0};
        float xa[2][4];

        for (int c = 0; c < 16; c++) {
            int buf = c & 1;
            if (c < 15) {
                int row = tid >> 3, col = tid & 7;
                cp16(spb + ((buf ^ 1) * 2048 + row * 32 + col * 4) * 4,
                     g_Pp + ((c + 1) * 64 + row) * 32 + col * 4);
                asm volatile("cp.async.commit_group;");
#pragma unroll
                for (int it = 0; it < 2; it++) {
                    int slot = tid + it * 512;
                    int k = slot & 63, tq = slot >> 6;
                    const float* src = x + (T0 + tq * 4) * 1024 + (c + 1) * 64 + k;
                    xa[it][0] = src[0]; xa[it][1] = src[1024];
                    xa[it][2] = src[2048]; xa[it][3] = src[3072];
                }
            }
            const float* xb = sXT + buf * 4352 + tg * 4;
            const float* pb = sP + buf * 2048 + og * 4;
#pragma unroll
            for (int kl = 0; kl < 16; kl++) {
                int k = ks * 16 + kl;
                float4 xv = *(const float4*)(xb + k * 68);
                ulonglong2 pp = *(const ulonglong2*)(pb + k * 32);
                ull x0 = dup_f(xv.x), x1 = dup_f(xv.y), x2 = dup_f(xv.z), x3 = dup_f(xv.w);
                FFMA2(acc[0], x0, pp.x); FFMA2(acc[1], x0, pp.y);
                FFMA2(acc[2], x1, pp.x); FFMA2(acc[3], x1, pp.y);
                FFMA2(acc[4], x2, pp.x); FFMA2(acc[5], x2, pp.y);
                FFMA2(acc[6], x3, pp.x); FFMA2(acc[7], x3, pp.y);
                if (og == 0) {
                    s1[0] += xv.x; s2[0] = fmaf(xv.x, xv.x, s2[0]);
                    s1[1] += xv.y; s2[1] = fmaf(xv.y, xv.y, s2[1]);
                    s1[2] += xv.z; s2[2] = fmaf(xv.z, xv.z, s2[2]);
                    s1[3] += xv.w; s2[3] = fmaf(xv.w, xv.w, s2[3]);
                }
            }
            if (c < 15) {
#pragma unroll
                for (int it = 0; it < 2; it++) {
                    int slot = tid + it * 512;
                    int k = slot & 63, tq = slot >> 6;
                    *(float4*)&sXT[(buf ^ 1) * 4352 + k * 68 + tq * 4] =
                        make_float4(xa[it][0], xa[it][1], xa[it][2], xa[it][3]);
                }
                asm volatile("cp.async.wait_group 0;");
            }
            __syncthreads();
        }

        // ---- combine k-splits + stats + epilogue ----
        float* Acm = dsm;          // 512 x 16
        float* B   = dsm + 8192;   // 64 x 8
        float* Cc  = dsm + 8704;   // mu[64], rs[64]
        if (ks > 0) {
            ull* d8 = (ull*)&Acm[tid * 16];
#pragma unroll
            for (int i = 0; i < 8; i++) d8[i] = acc[i];
        }
        if (og == 0) {
            float* sb = &B[(ks * 16 + tg) * 8];
#pragma unroll
            for (int j = 0; j < 4; j++) { sb[j] = s1[j]; sb[4 + j] = s2[j]; }
        }
        __syncthreads();
        if (tid < 64) {
            int tq = tid >> 2, j = tid & 3;
            float S1 = 0.f, S2 = 0.f;
#pragma unroll
            for (int k2 = 0; k2 < 4; k2++) {
                const float* bb = &B[(k2 * 16 + tq) * 8];
                S1 += bb[j];
                S2 += bb[4 + j];
            }
            float mu = S1 * (1.f / 1024.f);
            float var = S2 * (1.f / 1024.f) - mu * mu;
            Cc[tid] = mu;
            Cc[64 + tid] = rsqrtf(var + 1e-5f);
        }
        if (ks == 0) {
#pragma unroll
            for (int k2 = 1; k2 < 4; k2++) {
                const ull* src = (const ull*)&Acm[(tid + k2 * 16) * 16];
#pragma unroll
                for (int i = 0; i < 8; i++) ADD2(acc[i], src[i]);
            }
        }
        __syncthreads();
        if (ks == 0) {
            float mu[4], rs[4];
#pragma unroll
            for (int j = 0; j < 4; j++) { mu[j] = Cc[tg * 4 + j]; rs[j] = Cc[64 + tg * 4 + j]; }
            int b = T0 >> 12;
            int s0 = (T0 & 4095) + tg * 4;
#pragma unroll
            for (int i = 0; i < 4; i++) {
                int o = og * 4 + i;
                float k1v = g_k1[o];
                float k2v = g_k2[o] + g_c[o];
                float v[4];
#pragma unroll
                for (int j = 0; j < 4; j++) {
                    float lo, hi;
                    unpk(lo, hi, acc[j * 2 + (i >> 1)]);
                    float val = (i & 1) ? hi : lo;
                    val = rs[j] * val - mu[j] * rs[j] * k1v + k2v;
                    if (o < 16) val = 1.f / (1.f + __expf(-val));
                    v[j] = val;
                }
                *(float4*)&g_au[(b * 32 + o) * 4096 + s0] = make_float4(v[0], v[1], v[2], v[3]);
            }
        }
    }
    gsync();

    // ================= Phase D: scan (0-31) | fold-MT (32-63) =================
    if (blk < 32) {
        __shared__ float wA[16], wU[16], pU[16];
        int bn = blk;
        int b = bn >> 4, n = bn & 15;
        const float* ap = g_au + (b * 32 + n) * 4096;
        const float* up = g_au + (b * 32 + 16 + n) * 4096;

        float a[8], u[8];
        const float4* a4 = (const float4*)(ap + tid * 8);
        const float4* u4 = (const float4*)(up + tid * 8);
#pragma unroll
        for (int q = 0; q < 2; q++) {
            float4 av = a4[q], uv = u4[q];
            a[q*4+0] = av.x; a[q*4+1] = av.y; a[q*4+2] = av.z; a[q*4+3] = av.w;
            u[q*4+0] = uv.x; u[q*4+1] = uv.y; u[q*4+2] = uv.z; u[q*4+3] = uv.w;
        }
        float Aloc = 1.f, Uloc = 0.f;
#pragma unroll
        for (int i = 0; i < 8; i++) { Uloc = Uloc * a[i] + u[i]; Aloc *= a[i]; }

        float Ai = Aloc, Ui = Uloc;
#pragma unroll
        for (int off = 1; off < 32; off <<= 1) {
            float Ap = __shfl_up_sync(0xffffffffu, Ai, off);
            float Up = __shfl_up_sync(0xffffffffu, Ui, off);
            if (lane >= off) { Ui = Up * Ai + Ui; Ai = Ap * Ai; }
        }
        if (lane == 31) { wA[wid] = Ai; wU[wid] = Ui; }
        __syncthreads();
        if (tid == 0) {
            float Uc = 0.f;
#pragma unroll
            for (int j = 0; j < 16; j++) {
                pU[j] = Uc;
                Uc = Uc * wA[j] + wU[j];
            }
        }
        __syncthreads();
        float eA = __shfl_up_sync(0xffffffffu, Ai, 1);
        float eU = __shfl_up_sync(0xffffffffu, Ui, 1);
        if (lane == 0) { eA = 1.f; eU = 0.f; }
        float s = pU[wid] * eA + eU;

        float o8[8];
#pragma unroll
        for (int i = 0; i < 8; i++) { s = a[i] * s + u[i]; o8[i] = s; }
        float4* dst = (float4*)(g_states + bn * 4096 + tid * 8);
#pragma unroll
        for (int q = 0; q < 2; q++)
            dst[q] = make_float4(o8[q*4+0], o8[q*4+1], o8[q*4+2], o8[q*4+3]);
    } else if (blk < 64) {
        int base = (blk - 32) * 512 + tid;
        int d = base & 1023, n = base >> 10;
        float s = 0.f;
#pragma unroll
        for (int q = 0; q < 8; q++) s += g_MTp[(q * 16 + n) * 1024 + d];
        g_MT[n * 1024 + d] = s;
    }
    gsync();

    // ================= Phase E: out =================
    {
        float* sST = dsm;   // 64 tokens x 17
        int T0 = blk * 64;
        int b = T0 >> 12, s0 = T0 & 4095;
#pragma unroll
        for (int it = 0; it < 2; it++) {
            int idx = tid + it * 512;
            int soff = idx & 63, n = idx >> 6;
            sST[soff * 17 + n] = g_states[(b * 16 + n) * 4096 + s0 + soff];
        }
        int dq = tid & 255;
        int th = tid >> 8;
        ull m01[16], m23[16];
#pragma unroll
        for (int n = 0; n < 16; n++) {
            ulonglong2 mm = *(const ulonglong2*)(g_MT + n * 1024 + dq * 4);
            m01[n] = mm.x; m23[n] = mm.y;
        }
        ulonglong2 bov = *(const ulonglong2*)(bo + dq * 4);
        __syncthreads();

        for (int tl = 0; tl < 32; tl++) {
            int t = th * 32 + tl;
            ulonglong2 xv = *(const ulonglong2*)(x + (T0 + t) * 1024 + dq * 4);
            ull r01, r23;
            asm("add.rn.f32x2 %0, %1, %2;" : "=l"(r01) : "l"(xv.x), "l"(bov.x));
            asm("add.rn.f32x2 %0, %1, %2;" : "=l"(r23) : "l"(xv.y), "l"(bov.y));
#pragma unroll
            for (int n = 0; n < 16; n++) {
                ull sv = dup_f(sST[t * 17 + n]);
                FFMA2(r01, sv, m01[n]);
                FFMA2(r23, sv, m23[n]);
            }
            ulonglong2 res; res.x = r01; res.y = r23;
            *(ulonglong2*)(out + (T0 + t) * 1024 + dq * 4) = res;
        }
    }
}

// ---------------- launch ----------------
extern "C" void kernel_launch(void* const* d_in, const int* in_sizes, int n_in,
                              void* d_out, int out_size) {
    const float* x    = (const float*)d_in[0];
    const float* nw   = (const float*)d_in[1];
    const float* nb   = (const float*)d_in[2];
    const float* Win  = (const float*)d_in[3];
    const float* b_in = (const float*)d_in[4];
    const float* A    = (const float*)d_in[5];
    const float* Bs   = (const float*)d_in[6];
    const float* C    = (const float*)d_in[7];
    const float* Wout = (const float*)d_in[8];
    const float* bo   = (const float*)d_in[9];
    float* out = (float*)d_out;

    cudaFuncSetAttribute(k_main, cudaFuncAttributeMaxDynamicSharedMemorySize, 69632);

    k_main<<<GRID, NT, 67584>>>(x, nw, nb, Win, b_in, A, Bs, C, Wout, bo, out);
}